// round 2
// baseline (speedup 1.0000x reference)
#include <cuda_runtime.h>
#include <cuda_bf16.h>
#include <mma.h>
#include <cstdint>

using namespace nvcuda;

// Problem constants
#define BB 4
#define SS 2048
#define EE 1024
#define HH 16
#define DD 64
#define MTOT (BB * SS)   // 8192

// ---------------------------------------------------------------------------
// Scratch (no allocations allowed): Q/K/V in [B,H,S,D], attention out in [B,S,E]
// ---------------------------------------------------------------------------
__device__ float g_Q[BB * HH * SS * DD];
__device__ float g_K[BB * HH * SS * DD];
__device__ float g_V[BB * HH * SS * DD];
__device__ float g_O[BB * SS * EE];

__device__ __forceinline__ float to_tf32(float x) {
    uint32_t u;
    asm("cvt.rna.tf32.f32 %0, %1;" : "=r"(u) : "f"(x));
    return __uint_as_float(u);
}

// ---------------------------------------------------------------------------
// GEMM + bias:  Y = X[M,K] @ W[K,N] + b
// MODE 0: Y stored [M,N] (output projection, straight to d_out)
// MODE 1: Y stored [B,H,S,D] (head-split for attention); relies on BN == D == 64
// Tiles: BM=128, BN=64, BK=32. 256 threads = 8 warps, warp grid 4(M) x 2(N),
// each warp 32x32 = 2x2 wmma m16n16k8 tf32 tiles.
// ---------------------------------------------------------------------------
#define GBM 128
#define GBN 64
#define GBK 32
#define GLDA 40   // 32 + 8 pad
#define GLDB 72   // 64 + 8 pad
#define GLDC 68   // 64 + 4 pad

template <int MODE>
__global__ void __launch_bounds__(256) gemm_bias_k(
    const float* __restrict__ X, const float* __restrict__ W,
    const float* __restrict__ bias, float* __restrict__ Y)
{
    extern __shared__ float sm[];
    float* As = sm;                    // GBM * GLDA = 5120
    float* Bs = As + GBM * GLDA;       // GBK * GLDB = 2304
    float* Cs = Bs + GBK * GLDB;       // GBM * GLDC = 8704

    const int tid = threadIdx.x;
    const int wid = tid >> 5;
    const int wm = wid >> 1;           // 0..3
    const int wn = wid & 1;            // 0..1
    const int m0 = blockIdx.y * GBM;
    const int n0 = blockIdx.x * GBN;

    wmma::fragment<wmma::accumulator, 16, 16, 8, float> acc[2][2];
#pragma unroll
    for (int i = 0; i < 2; i++)
#pragma unroll
        for (int j = 0; j < 2; j++) wmma::fill_fragment(acc[i][j], 0.0f);

    for (int kk = 0; kk < EE; kk += GBK) {
        // A tile: 128x32 = 1024 float4
#pragma unroll
        for (int it = 0; it < 4; it++) {
            int idx = tid + it * 256;
            int r = idx >> 3;
            int c = (idx & 7) * 4;
            float4 v = *reinterpret_cast<const float4*>(
                &X[(size_t)(m0 + r) * EE + kk + c]);
            float* d = &As[r * GLDA + c];
            d[0] = to_tf32(v.x); d[1] = to_tf32(v.y);
            d[2] = to_tf32(v.z); d[3] = to_tf32(v.w);
        }
        // B tile: 32x64 = 512 float4
#pragma unroll
        for (int it = 0; it < 2; it++) {
            int idx = tid + it * 256;
            int r = idx >> 4;
            int c = (idx & 15) * 4;
            float4 v = *reinterpret_cast<const float4*>(
                &W[(size_t)(kk + r) * EE + n0 + c]);
            float* d = &Bs[r * GLDB + c];
            d[0] = to_tf32(v.x); d[1] = to_tf32(v.y);
            d[2] = to_tf32(v.z); d[3] = to_tf32(v.w);
        }
        __syncthreads();

#pragma unroll
        for (int ks = 0; ks < GBK; ks += 8) {
            wmma::fragment<wmma::matrix_a, 16, 16, 8, wmma::precision::tf32,
                           wmma::row_major> a[2];
            wmma::fragment<wmma::matrix_b, 16, 16, 8, wmma::precision::tf32,
                           wmma::row_major> b[2];
            wmma::load_matrix_sync(a[0], &As[(wm * 32 + 0) * GLDA + ks], GLDA);
            wmma::load_matrix_sync(a[1], &As[(wm * 32 + 16) * GLDA + ks], GLDA);
            wmma::load_matrix_sync(b[0], &Bs[ks * GLDB + wn * 32 + 0], GLDB);
            wmma::load_matrix_sync(b[1], &Bs[ks * GLDB + wn * 32 + 16], GLDB);
#pragma unroll
            for (int i = 0; i < 2; i++)
#pragma unroll
                for (int j = 0; j < 2; j++)
                    wmma::mma_sync(acc[i][j], a[i], b[j], acc[i][j]);
        }
        __syncthreads();
    }

    // Stage accumulators to shared, then fused bias + layout-transform store.
#pragma unroll
    for (int i = 0; i < 2; i++)
#pragma unroll
        for (int j = 0; j < 2; j++)
            wmma::store_matrix_sync(
                &Cs[(wm * 32 + i * 16) * GLDC + wn * 32 + j * 16],
                acc[i][j], GLDC, wmma::mem_row_major);
    __syncthreads();

#pragma unroll
    for (int it = 0; it < 8; it++) {
        int idx = tid + it * 256;       // 2048 float4 = 128x64
        int r = idx >> 4;
        int c = (idx & 15) * 4;
        int m = m0 + r;
        float4 v = *reinterpret_cast<const float4*>(&Cs[r * GLDC + c]);
        float4 bv = *reinterpret_cast<const float4*>(&bias[n0 + c]);
        v.x += bv.x; v.y += bv.y; v.z += bv.z; v.w += bv.w;
        if (MODE == 0) {
            *reinterpret_cast<float4*>(&Y[(size_t)m * EE + n0 + c]) = v;
        } else {
            int b = m >> 11;            // m / 2048
            int s = m & 2047;
            int h = blockIdx.x;         // BN == 64 == D -> n-tile index is head
            *reinterpret_cast<float4*>(
                &Y[(((size_t)(b * HH + h) * SS + s) * DD) + c]) = v;
        }
    }
}

// ---------------------------------------------------------------------------
// Causal flash attention, one (64-row Q tile, head) per block, 128 threads.
// Q,K,V in [B,H,S,D] fp32 (tile = contiguous 16KB block). Online softmax with
// O accumulated in shared (per-row rescale done in smem; wmma round-trips it).
// Writes O in [B,S,E] layout for the output projection.
// ---------------------------------------------------------------------------
#define ALD 72          // 64 + 8 pad
#define ATILE (64 * ALD)

__global__ void __launch_bounds__(128) attn_k(
    const float* __restrict__ Qh, const float* __restrict__ Kh,
    const float* __restrict__ Vh, float* __restrict__ O)
{
    extern __shared__ float sm[];
    float* Qs = sm;
    float* Ks = Qs + ATILE;
    float* Vs = Ks + ATILE;
    float* Ss = Vs + ATILE;
    float* Os = Ss + ATILE;
    float* m_s  = Os + ATILE;     // 64
    float* l_s  = m_s + 64;       // 64
    float* redm = l_s + 64;       // 2*64
    float* reds = redm + 128;     // 2*64

    const int tid = threadIdx.x;
    const int wid = tid >> 5;
    const int qi = blockIdx.x;    // 0..31
    const int bh = blockIdx.y;    // 0..63
    const size_t base = (size_t)bh * SS * DD;
    const float scale = 0.125f;   // 1/sqrt(64)

    // Load + scale Q tile (contiguous 64x64 block)
    const float* Qg = Qh + base + (size_t)qi * 64 * DD;
#pragma unroll
    for (int it = 0; it < 8; it++) {
        int idx = tid + it * 128;   // 1024 float4
        int r = idx >> 4;
        int c = (idx & 15) * 4;
        float4 v = *reinterpret_cast<const float4*>(&Qg[r * DD + c]);
        float* d = &Qs[r * ALD + c];
        d[0] = to_tf32(v.x * scale); d[1] = to_tf32(v.y * scale);
        d[2] = to_tf32(v.z * scale); d[3] = to_tf32(v.w * scale);
    }
    // Init O accumulator + stats
#pragma unroll
    for (int it = 0; it < 8; it++) {
        int idx = tid + it * 128;
        int r = idx >> 4;
        int c = (idx & 15) * 4;
        float4 z = make_float4(0.f, 0.f, 0.f, 0.f);
        *reinterpret_cast<float4*>(&Os[r * ALD + c]) = z;
    }
    if (tid < 64) { m_s[tid] = -1e30f; l_s[tid] = 0.0f; }
    __syncthreads();

    const int row = tid & 63;
    const int half = tid >> 6;
    const int c0 = half * 32;

    for (int j = 0; j <= qi; j++) {
        // ---- load K, V tiles (each contiguous 64x64) ----
        const float* Kg = Kh + base + (size_t)j * 64 * DD;
        const float* Vg = Vh + base + (size_t)j * 64 * DD;
#pragma unroll
        for (int it = 0; it < 8; it++) {
            int idx = tid + it * 128;
            int r = idx >> 4;
            int c = (idx & 15) * 4;
            float4 kv = *reinterpret_cast<const float4*>(&Kg[r * DD + c]);
            float4 vv = *reinterpret_cast<const float4*>(&Vg[r * DD + c]);
            float* dk = &Ks[r * ALD + c];
            float* dv = &Vs[r * ALD + c];
            dk[0] = to_tf32(kv.x); dk[1] = to_tf32(kv.y);
            dk[2] = to_tf32(kv.z); dk[3] = to_tf32(kv.w);
            dv[0] = to_tf32(vv.x); dv[1] = to_tf32(vv.y);
            dv[2] = to_tf32(vv.z); dv[3] = to_tf32(vv.w);
        }
        __syncthreads();

        // ---- S = (Q*scale) @ K^T : each warp a 16x64 strip ----
        {
            wmma::fragment<wmma::accumulator, 16, 16, 8, float> sacc[4];
#pragma unroll
            for (int n = 0; n < 4; n++) wmma::fill_fragment(sacc[n], 0.0f);
#pragma unroll
            for (int ks = 0; ks < 64; ks += 8) {
                wmma::fragment<wmma::matrix_a, 16, 16, 8, wmma::precision::tf32,
                               wmma::row_major> a;
                wmma::load_matrix_sync(a, &Qs[(wid * 16) * ALD + ks], ALD);
#pragma unroll
                for (int n = 0; n < 4; n++) {
                    wmma::fragment<wmma::matrix_b, 16, 16, 8,
                                   wmma::precision::tf32, wmma::col_major> b;
                    wmma::load_matrix_sync(b, &Ks[(n * 16) * ALD + ks], ALD);
                    wmma::mma_sync(sacc[n], a, b, sacc[n]);
                }
            }
#pragma unroll
            for (int n = 0; n < 4; n++)
                wmma::store_matrix_sync(&Ss[(wid * 16) * ALD + n * 16],
                                        sacc[n], ALD, wmma::mem_row_major);
        }
        __syncthreads();

        // ---- online softmax: 2 threads per row, 32 cols each ----
        const bool diag = (j == qi);
        float mx = -1e30f;
#pragma unroll
        for (int c = 0; c < 32; c++) {
            float s = Ss[row * ALD + c0 + c];
            if (diag && (c0 + c) > row) s = -1e30f;
            mx = fmaxf(mx, s);
        }
        redm[half * 64 + row] = mx;
        __syncthreads();

        float mtile = fmaxf(redm[row], redm[64 + row]);
        float mold = m_s[row];
        float mnew = fmaxf(mold, mtile);
        float corr = __expf(mold - mnew);
        float sum = 0.0f;
#pragma unroll
        for (int c = 0; c < 32; c++) {
            float s = Ss[row * ALD + c0 + c];
            if (diag && (c0 + c) > row) s = -1e30f;
            float p = __expf(s - mnew);
            sum += p;
            Ss[row * ALD + c0 + c] = to_tf32(p);
        }
        reds[half * 64 + row] = sum;
        // rescale O rows (this thread's 32-col segment)
#pragma unroll
        for (int c = 0; c < 32; c++) Os[row * ALD + c0 + c] *= corr;
        __syncthreads();

        if (half == 0) {
            l_s[row] = l_s[row] * corr + reds[row] + reds[64 + row];
            m_s[row] = mnew;
        }

        // ---- O += P @ V : each warp a 16x64 strip ----
        {
            wmma::fragment<wmma::accumulator, 16, 16, 8, float> oacc[4];
#pragma unroll
            for (int n = 0; n < 4; n++)
                wmma::load_matrix_sync(oacc[n], &Os[(wid * 16) * ALD + n * 16],
                                       ALD, wmma::mem_row_major);
#pragma unroll
            for (int ks = 0; ks < 64; ks += 8) {
                wmma::fragment<wmma::matrix_a, 16, 16, 8, wmma::precision::tf32,
                               wmma::row_major> a;
                wmma::load_matrix_sync(a, &Ss[(wid * 16) * ALD + ks], ALD);
#pragma unroll
                for (int n = 0; n < 4; n++) {
                    wmma::fragment<wmma::matrix_b, 16, 16, 8,
                                   wmma::precision::tf32, wmma::row_major> b;
                    wmma::load_matrix_sync(b, &Vs[ks * ALD + n * 16], ALD);
                    wmma::mma_sync(oacc[n], a, b, oacc[n]);
                }
            }
#pragma unroll
            for (int n = 0; n < 4; n++)
                wmma::store_matrix_sync(&Os[(wid * 16) * ALD + n * 16],
                                        oacc[n], ALD, wmma::mem_row_major);
        }
        __syncthreads();
    }

    // ---- normalize + write O in [B, S, E] layout ----
    const float inv = 1.0f / l_s[row];
    const int s_glob = qi * 64 + row;
    const int b = bh >> 4;
    const int h = bh & 15;
    float* Og = O + ((size_t)b * SS + s_glob) * EE + h * 64;
#pragma unroll
    for (int c = 0; c < 32; c += 4) {
        float4 v = *reinterpret_cast<const float4*>(&Os[row * ALD + c0 + c]);
        v.x *= inv; v.y *= inv; v.z *= inv; v.w *= inv;
        *reinterpret_cast<float4*>(&Og[c0 + c]) = v;
    }
}

// ---------------------------------------------------------------------------
// Launch
// ---------------------------------------------------------------------------
extern "C" void kernel_launch(void* const* d_in, const int* in_sizes, int n_in,
                              void* d_out, int out_size)
{
    const float* q   = (const float*)d_in[0];
    const float* k   = (const float*)d_in[1];
    const float* v   = (const float*)d_in[2];
    const float* w_q = (const float*)d_in[3];
    const float* b_q = (const float*)d_in[4];
    const float* w_k = (const float*)d_in[5];
    const float* b_k = (const float*)d_in[6];
    const float* w_v = (const float*)d_in[7];
    const float* b_v = (const float*)d_in[8];
    const float* w_o = (const float*)d_in[9];
    const float* b_o = (const float*)d_in[10];
    float* out = (float*)d_out;

    const int gemm_smem = (GBM * GLDA + GBK * GLDB + GBM * GLDC) * 4;  // 64512
    const int attn_smem = (5 * ATILE + 64 + 64 + 128 + 128) * 4;        // 93696

    cudaFuncSetAttribute(gemm_bias_k<0>,
                         cudaFuncAttributeMaxDynamicSharedMemorySize, gemm_smem);
    cudaFuncSetAttribute(gemm_bias_k<1>,
                         cudaFuncAttributeMaxDynamicSharedMemorySize, gemm_smem);
    cudaFuncSetAttribute(attn_k,
                         cudaFuncAttributeMaxDynamicSharedMemorySize, attn_smem);

    float* gQ;  cudaGetSymbolAddress((void**)&gQ, g_Q);
    float* gK;  cudaGetSymbolAddress((void**)&gK, g_K);
    float* gV;  cudaGetSymbolAddress((void**)&gV, g_V);
    float* gO;  cudaGetSymbolAddress((void**)&gO, g_O);

    dim3 ggrid(EE / GBN, MTOT / GBM);  // (16, 64)

    gemm_bias_k<1><<<ggrid, 256, gemm_smem>>>(q, w_q, b_q, gQ);
    gemm_bias_k<1><<<ggrid, 256, gemm_smem>>>(k, w_k, b_k, gK);
    gemm_bias_k<1><<<ggrid, 256, gemm_smem>>>(v, w_v, b_v, gV);

    attn_k<<<dim3(SS / 64, BB * HH), 128, attn_smem>>>(gQ, gK, gV, gO);

    gemm_bias_k<0><<<ggrid, 256, gemm_smem>>>(gO, w_o, b_o, out);
}

// round 3
// speedup vs baseline: 1.4424x; 1.4424x over previous
#include <cuda_runtime.h>
#include <cuda_bf16.h>
#include <mma.h>
#include <cstdint>

using namespace nvcuda;

// Problem constants
#define BB 4
#define SS 2048
#define EE 1024
#define HH 16
#define DD 64
#define MTOT (BB * SS)   // 8192

// ---------------------------------------------------------------------------
// Scratch
// ---------------------------------------------------------------------------
__device__ float g_Q[BB * HH * SS * DD];
__device__ float g_K[BB * HH * SS * DD];
__device__ float g_V[BB * HH * SS * DD];
__device__ float g_O[BB * SS * EE];

__device__ __forceinline__ float to_tf32(float x) {
    uint32_t u;
    asm("cvt.rna.tf32.f32 %0, %1;" : "=r"(u) : "f"(x));
    return __uint_as_float(u);
}

// mma.sync m16n8k8 tf32: D += A(16x8 row) * B(8x8 col)
__device__ __forceinline__ void mma16n8k8(float d[4], const uint32_t a[4],
                                          uint32_t b0, uint32_t b1) {
    asm volatile(
        "mma.sync.aligned.m16n8k8.row.col.f32.tf32.tf32.f32 "
        "{%0,%1,%2,%3}, {%4,%5,%6,%7}, {%8,%9}, {%0,%1,%2,%3};\n"
        : "+f"(d[0]), "+f"(d[1]), "+f"(d[2]), "+f"(d[3])
        : "r"(a[0]), "r"(a[1]), "r"(a[2]), "r"(a[3]), "r"(b0), "r"(b1));
}

// ---------------------------------------------------------------------------
// GEMM + bias:  Y = X[M,K] @ W[K,N] + b   (double-buffered smem, wmma tf32)
// MODE 0: Y [M,N]; MODE 1: Y [B,H,S,D] (BN == D == 64)
// ---------------------------------------------------------------------------
#define GBM 128
#define GBN 64
#define GBK 32
#define GLDA 40   // 32 + 8 pad
#define GLDB 72   // 64 + 8 pad
#define GLDC 68   // 64 + 4 pad

template <int MODE>
__global__ void __launch_bounds__(256) gemm_bias_k(
    const float* __restrict__ X, const float* __restrict__ W,
    const float* __restrict__ bias, float* __restrict__ Y)
{
    extern __shared__ float sm[];
    float* As0 = sm;                        // 5120
    float* As1 = As0 + GBM * GLDA;          // 5120
    float* Bs0 = As1 + GBM * GLDA;          // 2304
    float* Bs1 = Bs0 + GBK * GLDB;          // 2304
    float* Cs  = Bs1 + GBK * GLDB;          // 8704

    const int tid = threadIdx.x;
    const int wid = tid >> 5;
    const int wm = wid >> 1;
    const int wn = wid & 1;
    const int m0 = blockIdx.y * GBM;
    const int n0 = blockIdx.x * GBN;

    wmma::fragment<wmma::accumulator, 16, 16, 8, float> acc[2][2];
#pragma unroll
    for (int i = 0; i < 2; i++)
#pragma unroll
        for (int j = 0; j < 2; j++) wmma::fill_fragment(acc[i][j], 0.0f);

    // preload stage 0
    {
#pragma unroll
        for (int it = 0; it < 4; it++) {
            int idx = tid + it * 256;
            int r = idx >> 3, cc = (idx & 7) * 4;
            float4 v = *reinterpret_cast<const float4*>(&X[(size_t)(m0 + r) * EE + cc]);
            float* d = &As0[r * GLDA + cc];
            d[0] = to_tf32(v.x); d[1] = to_tf32(v.y);
            d[2] = to_tf32(v.z); d[3] = to_tf32(v.w);
        }
#pragma unroll
        for (int it = 0; it < 2; it++) {
            int idx = tid + it * 256;
            int r = idx >> 4, cc = (idx & 15) * 4;
            float4 v = *reinterpret_cast<const float4*>(&W[(size_t)r * EE + n0 + cc]);
            float* d = &Bs0[r * GLDB + cc];
            d[0] = to_tf32(v.x); d[1] = to_tf32(v.y);
            d[2] = to_tf32(v.z); d[3] = to_tf32(v.w);
        }
    }
    __syncthreads();

    const int NS = EE / GBK;  // 32
    for (int s = 0; s < NS; s++) {
        float* As = (s & 1) ? As1 : As0;
        float* Bs = (s & 1) ? Bs1 : Bs0;
        const bool pf = (s + 1 < NS);
        float4 ra[4], rb[2];
        if (pf) {
            int kb = (s + 1) * GBK;
#pragma unroll
            for (int it = 0; it < 4; it++) {
                int idx = tid + it * 256;
                int r = idx >> 3, cc = (idx & 7) * 4;
                ra[it] = *reinterpret_cast<const float4*>(
                    &X[(size_t)(m0 + r) * EE + kb + cc]);
            }
#pragma unroll
            for (int it = 0; it < 2; it++) {
                int idx = tid + it * 256;
                int r = idx >> 4, cc = (idx & 15) * 4;
                rb[it] = *reinterpret_cast<const float4*>(
                    &W[(size_t)(kb + r) * EE + n0 + cc]);
            }
        }

#pragma unroll
        for (int ks = 0; ks < GBK; ks += 8) {
            wmma::fragment<wmma::matrix_a, 16, 16, 8, wmma::precision::tf32,
                           wmma::row_major> a[2];
            wmma::fragment<wmma::matrix_b, 16, 16, 8, wmma::precision::tf32,
                           wmma::row_major> b[2];
            wmma::load_matrix_sync(a[0], &As[(wm * 32 + 0) * GLDA + ks], GLDA);
            wmma::load_matrix_sync(a[1], &As[(wm * 32 + 16) * GLDA + ks], GLDA);
            wmma::load_matrix_sync(b[0], &Bs[ks * GLDB + wn * 32 + 0], GLDB);
            wmma::load_matrix_sync(b[1], &Bs[ks * GLDB + wn * 32 + 16], GLDB);
#pragma unroll
            for (int i = 0; i < 2; i++)
#pragma unroll
                for (int j = 0; j < 2; j++)
                    wmma::mma_sync(acc[i][j], a[i], b[j], acc[i][j]);
        }

        if (pf) {
            float* Ad = (s & 1) ? As0 : As1;
            float* Bd = (s & 1) ? Bs0 : Bs1;
#pragma unroll
            for (int it = 0; it < 4; it++) {
                int idx = tid + it * 256;
                int r = idx >> 3, cc = (idx & 7) * 4;
                float* d = &Ad[r * GLDA + cc];
                d[0] = to_tf32(ra[it].x); d[1] = to_tf32(ra[it].y);
                d[2] = to_tf32(ra[it].z); d[3] = to_tf32(ra[it].w);
            }
#pragma unroll
            for (int it = 0; it < 2; it++) {
                int idx = tid + it * 256;
                int r = idx >> 4, cc = (idx & 15) * 4;
                float* d = &Bd[r * GLDB + cc];
                d[0] = to_tf32(rb[it].x); d[1] = to_tf32(rb[it].y);
                d[2] = to_tf32(rb[it].z); d[3] = to_tf32(rb[it].w);
            }
        }
        __syncthreads();
    }

    // epilogue: stage accumulators, fused bias + layout-transform store
#pragma unroll
    for (int i = 0; i < 2; i++)
#pragma unroll
        for (int j = 0; j < 2; j++)
            wmma::store_matrix_sync(
                &Cs[(wm * 32 + i * 16) * GLDC + wn * 32 + j * 16],
                acc[i][j], GLDC, wmma::mem_row_major);
    __syncthreads();

#pragma unroll
    for (int it = 0; it < 8; it++) {
        int idx = tid + it * 256;
        int r = idx >> 4, cc = (idx & 15) * 4;
        int m = m0 + r;
        float4 v = *reinterpret_cast<const float4*>(&Cs[r * GLDC + cc]);
        float4 bv = *reinterpret_cast<const float4*>(&bias[n0 + cc]);
        v.x += bv.x; v.y += bv.y; v.z += bv.z; v.w += bv.w;
        if (MODE == 0) {
            *reinterpret_cast<float4*>(&Y[(size_t)m * EE + n0 + cc]) = v;
        } else {
            int b = m >> 11;
            int ss = m & 2047;
            int h = blockIdx.x;
            *reinterpret_cast<float4*>(
                &Y[(((size_t)(b * HH + h) * SS + ss) * DD) + cc]) = v;
        }
    }
}

// ---------------------------------------------------------------------------
// Flash attention: 256 threads, Q-tile 128x64 per CTA, register-resident
// S and O via mma.m16n8k8 tf32. K/V tiles (64 rows) double-buffered in smem.
// ---------------------------------------------------------------------------
#define AKLD 68                  // K tile pad: banks 4r+c conflict-free
#define AVLD 72                  // V tile pad: banks 8c+r conflict-free
#define KBUFF (64 * AKLD)        // 4352 floats
#define VBUFF (64 * AVLD)        // 4608 floats
#define ASMEM ((2 * KBUFF + 2 * VBUFF) * 4)   // 71680 bytes

__global__ void __launch_bounds__(256) attn_k(
    const float* __restrict__ Qh, const float* __restrict__ Kh,
    const float* __restrict__ Vh, float* __restrict__ O)
{
    extern __shared__ float sm[];
    float* K0 = sm;
    float* K1 = sm + KBUFF;
    float* V0 = sm + 2 * KBUFF;
    float* V1 = V0 + VBUFF;

    const int tid = threadIdx.x;
    const int lane = tid & 31;
    const int w = tid >> 5;
    const int r = lane >> 2;         // 0..7
    const int c = lane & 3;          // 0..3
    const int qi = blockIdx.x;       // 0..15
    const int bh = blockIdx.y;       // 0..63
    const size_t base = (size_t)bh * SS * DD;
    const int q0 = qi * 128;
    const int rw = q0 + w * 16;      // warp row base

    // ---- stage Q (128x64) into smem (first 128*68 floats = 2 K buffers)
    {
        const float* Qg = Qh + base + (size_t)q0 * DD;
#pragma unroll
        for (int it = 0; it < 8; it++) {
            int g = it * 256 + tid;
            int row = g >> 4, c4 = (g & 15) * 4;
            float4 v = *reinterpret_cast<const float4*>(&Qg[row * DD + c4]);
            float* d = &sm[row * AKLD + c4];
            d[0] = v.x; d[1] = v.y; d[2] = v.z; d[3] = v.w;
        }
    }
    __syncthreads();

    // ---- build Q A-fragments (scaled + tf32)
    uint32_t Qa[8][4];
    {
        const float scale = 0.125f;   // 1/sqrt(64)
#pragma unroll
        for (int k = 0; k < 8; k++) {
            int kc = k * 8;
            Qa[k][0] = __float_as_uint(to_tf32(sm[(w*16 + r)     * AKLD + kc + c]     * scale));
            Qa[k][1] = __float_as_uint(to_tf32(sm[(w*16 + r + 8) * AKLD + kc + c]     * scale));
            Qa[k][2] = __float_as_uint(to_tf32(sm[(w*16 + r)     * AKLD + kc + c + 4] * scale));
            Qa[k][3] = __float_as_uint(to_tf32(sm[(w*16 + r + 8) * AKLD + kc + c + 4] * scale));
        }
    }
    __syncthreads();

    // ---- load KV tile 0 (cvt to tf32 during staging)
    {
        const float* Kg = Kh + base;
        const float* Vg = Vh + base;
#pragma unroll
        for (int it = 0; it < 4; it++) {
            int g = it * 256 + tid;
            int row = g >> 4, c4 = (g & 15) * 4;
            float4 kv = *reinterpret_cast<const float4*>(&Kg[row * DD + c4]);
            float4 vv = *reinterpret_cast<const float4*>(&Vg[row * DD + c4]);
            float* dk = &K0[row * AKLD + c4];
            dk[0] = to_tf32(kv.x); dk[1] = to_tf32(kv.y);
            dk[2] = to_tf32(kv.z); dk[3] = to_tf32(kv.w);
            float* dv = &V0[row * AVLD + c4];
            dv[0] = to_tf32(vv.x); dv[1] = to_tf32(vv.y);
            dv[2] = to_tf32(vv.z); dv[3] = to_tf32(vv.w);
        }
    }
    __syncthreads();

    float Oa[8][4];
#pragma unroll
    for (int dn = 0; dn < 8; dn++)
#pragma unroll
        for (int e = 0; e < 4; e++) Oa[dn][e] = 0.0f;
    float m0 = -1e30f, m1 = -1e30f, l0 = 0.0f, l1 = 0.0f;

    const int jmax = 2 * qi + 1;
    const int src0 = (lane & ~3) | (c >> 1);   // S(C-layout) -> P(A-layout) shuffle srcs
    const int src1 = src0 + 2;
    const bool odd = (c & 1);

    for (int j = 0; j <= jmax; j++) {
        float* Ks = (j & 1) ? K1 : K0;
        float* Vs = (j & 1) ? V1 : V0;
        const bool pf = (j < jmax);
        float4 pk[4], pv[4];
        if (pf) {
            const float* Kg = Kh + base + (size_t)(j + 1) * 64 * DD;
            const float* Vg = Vh + base + (size_t)(j + 1) * 64 * DD;
#pragma unroll
            for (int it = 0; it < 4; it++) {
                int g = it * 256 + tid;
                int row = g >> 4, c4 = (g & 15) * 4;
                pk[it] = *reinterpret_cast<const float4*>(&Kg[row * DD + c4]);
                pv[it] = *reinterpret_cast<const float4*>(&Vg[row * DD + c4]);
            }
        }

        const bool active = (j * 64) <= (rw + 15);   // warp-uniform causal skip
        if (active) {
            // ---- S = Q @ K^T
            float Sa[8][4];
#pragma unroll
            for (int nt = 0; nt < 8; nt++)
#pragma unroll
                for (int e = 0; e < 4; e++) Sa[nt][e] = 0.0f;
#pragma unroll
            for (int k = 0; k < 8; k++) {
#pragma unroll
                for (int nt = 0; nt < 8; nt++) {
                    uint32_t b0 = __float_as_uint(Ks[(nt*8 + r) * AKLD + k*8 + c]);
                    uint32_t b1 = __float_as_uint(Ks[(nt*8 + r) * AKLD + k*8 + c + 4]);
                    mma16n8k8(Sa[nt], Qa[k], b0, b1);
                }
            }

            // ---- causal mask (only for diagonal tiles)
            if (j * 64 + 63 > rw) {
#pragma unroll
                for (int nt = 0; nt < 8; nt++) {
                    int colb = j * 64 + nt * 8 + 2 * c;
                    if (colb     > rw + r)     Sa[nt][0] = -1e30f;
                    if (colb + 1 > rw + r)     Sa[nt][1] = -1e30f;
                    if (colb     > rw + r + 8) Sa[nt][2] = -1e30f;
                    if (colb + 1 > rw + r + 8) Sa[nt][3] = -1e30f;
                }
            }

            // ---- online softmax (quad butterfly reductions)
            float t0 = -1e30f, t1 = -1e30f;
#pragma unroll
            for (int nt = 0; nt < 8; nt++) {
                t0 = fmaxf(t0, fmaxf(Sa[nt][0], Sa[nt][1]));
                t1 = fmaxf(t1, fmaxf(Sa[nt][2], Sa[nt][3]));
            }
            t0 = fmaxf(t0, __shfl_xor_sync(0xffffffffu, t0, 1));
            t0 = fmaxf(t0, __shfl_xor_sync(0xffffffffu, t0, 2));
            t1 = fmaxf(t1, __shfl_xor_sync(0xffffffffu, t1, 1));
            t1 = fmaxf(t1, __shfl_xor_sync(0xffffffffu, t1, 2));
            float mn0 = fmaxf(m0, t0), mn1 = fmaxf(m1, t1);
            float cr0 = __expf(m0 - mn0), cr1 = __expf(m1 - mn1);
            m0 = mn0; m1 = mn1;

            float rs0 = 0.0f, rs1 = 0.0f;
#pragma unroll
            for (int nt = 0; nt < 8; nt++) {
                Sa[nt][0] = __expf(Sa[nt][0] - mn0);
                Sa[nt][1] = __expf(Sa[nt][1] - mn0);
                Sa[nt][2] = __expf(Sa[nt][2] - mn1);
                Sa[nt][3] = __expf(Sa[nt][3] - mn1);
                rs0 += Sa[nt][0] + Sa[nt][1];
                rs1 += Sa[nt][2] + Sa[nt][3];
            }
            rs0 += __shfl_xor_sync(0xffffffffu, rs0, 1);
            rs0 += __shfl_xor_sync(0xffffffffu, rs0, 2);
            rs1 += __shfl_xor_sync(0xffffffffu, rs1, 1);
            rs1 += __shfl_xor_sync(0xffffffffu, rs1, 2);
            l0 = l0 * cr0 + rs0;
            l1 = l1 * cr1 + rs1;

#pragma unroll
            for (int dn = 0; dn < 8; dn++) {
                Oa[dn][0] *= cr0; Oa[dn][1] *= cr0;
                Oa[dn][2] *= cr1; Oa[dn][3] *= cr1;
            }

            // ---- O += P @ V   (S C-layout -> A-layout via quad shuffles)
#pragma unroll
            for (int nt = 0; nt < 8; nt++) {
                float p0 = to_tf32(Sa[nt][0]);
                float p1 = to_tf32(Sa[nt][1]);
                float p2 = to_tf32(Sa[nt][2]);
                float p3 = to_tf32(Sa[nt][3]);
                float x0 = __shfl_sync(0xffffffffu, p0, src0);
                float x1 = __shfl_sync(0xffffffffu, p1, src0);
                float y0 = __shfl_sync(0xffffffffu, p0, src1);
                float y1 = __shfl_sync(0xffffffffu, p1, src1);
                float z0 = __shfl_sync(0xffffffffu, p2, src0);
                float z1 = __shfl_sync(0xffffffffu, p3, src0);
                float u0 = __shfl_sync(0xffffffffu, p2, src1);
                float u1 = __shfl_sync(0xffffffffu, p3, src1);
                uint32_t A[4];
                A[0] = __float_as_uint(odd ? x1 : x0);  // (r,   q)
                A[1] = __float_as_uint(odd ? z1 : z0);  // (r+8, q)
                A[2] = __float_as_uint(odd ? y1 : y0);  // (r,   q+4)
                A[3] = __float_as_uint(odd ? u1 : u0);  // (r+8, q+4)
#pragma unroll
                for (int dn = 0; dn < 8; dn++) {
                    uint32_t b0 = __float_as_uint(Vs[(nt*8 + c)     * AVLD + dn*8 + r]);
                    uint32_t b1 = __float_as_uint(Vs[(nt*8 + c + 4) * AVLD + dn*8 + r]);
                    mma16n8k8(Oa[dn], A, b0, b1);
                }
            }
        }

        if (pf) {
            float* dK = (j & 1) ? K0 : K1;
            float* dV = (j & 1) ? V0 : V1;
#pragma unroll
            for (int it = 0; it < 4; it++) {
                int g = it * 256 + tid;
                int row = g >> 4, c4 = (g & 15) * 4;
                float* dk = &dK[row * AKLD + c4];
                dk[0] = to_tf32(pk[it].x); dk[1] = to_tf32(pk[it].y);
                dk[2] = to_tf32(pk[it].z); dk[3] = to_tf32(pk[it].w);
                float* dv = &dV[row * AVLD + c4];
                dv[0] = to_tf32(pv[it].x); dv[1] = to_tf32(pv[it].y);
                dv[2] = to_tf32(pv[it].z); dv[3] = to_tf32(pv[it].w);
            }
        }
        __syncthreads();
    }

    // ---- epilogue: normalize + write O in [B,S,E] layout
    const float inv0 = 1.0f / l0;
    const float inv1 = 1.0f / l1;
    const int b = bh >> 4, h = bh & 15;
    const int row0 = rw + r, row1 = rw + r + 8;
    float* O0 = O + ((size_t)b * SS + row0) * EE + h * 64;
    float* O1 = O + ((size_t)b * SS + row1) * EE + h * 64;
#pragma unroll
    for (int dn = 0; dn < 8; dn++) {
        int col = dn * 8 + 2 * c;
        float2 v0 = make_float2(Oa[dn][0] * inv0, Oa[dn][1] * inv0);
        float2 v1 = make_float2(Oa[dn][2] * inv1, Oa[dn][3] * inv1);
        *reinterpret_cast<float2*>(&O0[col]) = v0;
        *reinterpret_cast<float2*>(&O1[col]) = v1;
    }
}

// ---------------------------------------------------------------------------
// Launch
// ---------------------------------------------------------------------------
extern "C" void kernel_launch(void* const* d_in, const int* in_sizes, int n_in,
                              void* d_out, int out_size)
{
    const float* q   = (const float*)d_in[0];
    const float* k   = (const float*)d_in[1];
    const float* v   = (const float*)d_in[2];
    const float* w_q = (const float*)d_in[3];
    const float* b_q = (const float*)d_in[4];
    const float* w_k = (const float*)d_in[5];
    const float* b_k = (const float*)d_in[6];
    const float* w_v = (const float*)d_in[7];
    const float* b_v = (const float*)d_in[8];
    const float* w_o = (const float*)d_in[9];
    const float* b_o = (const float*)d_in[10];
    float* out = (float*)d_out;

    const int gemm_smem = (2 * (GBM * GLDA + GBK * GLDB) + GBM * GLDC) * 4; // 94208
    const int attn_smem = ASMEM;                                            // 71680

    cudaFuncSetAttribute(gemm_bias_k<0>,
                         cudaFuncAttributeMaxDynamicSharedMemorySize, gemm_smem);
    cudaFuncSetAttribute(gemm_bias_k<1>,
                         cudaFuncAttributeMaxDynamicSharedMemorySize, gemm_smem);
    cudaFuncSetAttribute(attn_k,
                         cudaFuncAttributeMaxDynamicSharedMemorySize, attn_smem);

    float* gQ;  cudaGetSymbolAddress((void**)&gQ, g_Q);
    float* gK;  cudaGetSymbolAddress((void**)&gK, g_K);
    float* gV;  cudaGetSymbolAddress((void**)&gV, g_V);
    float* gO;  cudaGetSymbolAddress((void**)&gO, g_O);

    dim3 ggrid(EE / GBN, MTOT / GBM);  // (16, 64)

    gemm_bias_k<1><<<ggrid, 256, gemm_smem>>>(q, w_q, b_q, gQ);
    gemm_bias_k<1><<<ggrid, 256, gemm_smem>>>(k, w_k, b_k, gK);
    gemm_bias_k<1><<<ggrid, 256, gemm_smem>>>(v, w_v, b_v, gV);

    attn_k<<<dim3(SS / 128, BB * HH), 256, attn_smem>>>(gQ, gK, gV, gO);

    gemm_bias_k<0><<<ggrid, 256, gemm_smem>>>(gO, w_o, b_o, out);
}